// round 1
// baseline (speedup 1.0000x reference)
#include <cuda_runtime.h>
#include <math.h>

#define BATCH 2
#define LSEQ  1024
#define DM    1024
#define DIN   2048
#define DTR   64
#define DST   16
#define XDBL_W (DTR + 2*DST)   /* 96 */
#define MTOK (BATCH*LSEQ)      /* 2048 */

// ---------------- scratch (device globals; no allocation allowed) ----------------
__device__ float g_xr   [(size_t)MTOK * 2 * DIN];   // x_and_res [2048, 4096]
__device__ float g_xconv[(size_t)MTOK * DIN];       // conv+silu output
__device__ float g_xdbl [(size_t)MTOK * XDBL_W];    // delta_in | B | C
__device__ float g_delta[(size_t)MTOK * DIN];       // softplus(delta)
__device__ float g_y    [(size_t)MTOK * DIN];       // scan output
__device__ float g_yc   [(size_t)MTOK * DIN];       // y * silu(res)

// ---------------- generic fp32 SGEMM: C[M,N] = A[M,K] @ B[K,N] ----------------
// BM=BN=64, BK=16, 256 threads, 4x4 microtile. M % 64 == 0, K % 16 == 0 required.
// N handled with bounds checks (needed for N=96).
// EPI==1: v = softplus(v + bias[col])
template<int EPI>
__global__ __launch_bounds__(256) void sgemm_k(
    const float* __restrict__ A, const float* __restrict__ B,
    const float* __restrict__ bias, float* __restrict__ C,
    int M, int N, int K, int lda, int ldb, int ldc)
{
    __shared__ __align__(16) float As[16][68];
    __shared__ __align__(16) float Bs[16][68];

    const int tid = threadIdx.x;
    const int tx = tid & 15;          // 0..15 -> 4 cols each
    const int ty = tid >> 4;          // 0..15 -> 4 rows each
    const int rowBase = blockIdx.y * 64;
    const int colBase = blockIdx.x * 64;

    // A tile load mapping: row = tid>>2 (0..63), k-offset = (tid&3)*4
    const int aRowL = tid >> 2;
    const int aK    = (tid & 3) * 4;
    const int aRow  = rowBase + aRowL;
    // B tile load mapping: k-row = tid>>4 (0..15), col-offset = (tid&15)*4
    const int bK   = tid >> 4;
    const int bCol = colBase + tx * 4;

    float acc[4][4] = {};

    for (int k0 = 0; k0 < K; k0 += 16) {
        // load A tile (always in bounds: M%64==0, K%16==0)
        float4 a4 = *(const float4*)(A + (size_t)aRow * lda + k0 + aK);
        As[aK + 0][aRowL] = a4.x;
        As[aK + 1][aRowL] = a4.y;
        As[aK + 2][aRowL] = a4.z;
        As[aK + 3][aRowL] = a4.w;

        // load B tile with N bounds guard
        float4 b4;
        if (bCol + 3 < N) {
            b4 = *(const float4*)(B + (size_t)(k0 + bK) * ldb + bCol);
        } else {
            const float* brow = B + (size_t)(k0 + bK) * ldb;
            b4.x = (bCol + 0 < N) ? brow[bCol + 0] : 0.f;
            b4.y = (bCol + 1 < N) ? brow[bCol + 1] : 0.f;
            b4.z = (bCol + 2 < N) ? brow[bCol + 2] : 0.f;
            b4.w = (bCol + 3 < N) ? brow[bCol + 3] : 0.f;
        }
        *(float4*)&Bs[bK][tx * 4] = b4;

        __syncthreads();

        #pragma unroll
        for (int kk = 0; kk < 16; kk++) {
            float4 av = *(const float4*)&As[kk][ty * 4];
            float4 bv = *(const float4*)&Bs[kk][tx * 4];
            float a[4] = {av.x, av.y, av.z, av.w};
            float b[4] = {bv.x, bv.y, bv.z, bv.w};
            #pragma unroll
            for (int i = 0; i < 4; i++)
                #pragma unroll
                for (int j = 0; j < 4; j++)
                    acc[i][j] = fmaf(a[i], b[j], acc[i][j]);
        }
        __syncthreads();
    }

    #pragma unroll
    for (int i = 0; i < 4; i++) {
        const int r = rowBase + ty * 4 + i;
        #pragma unroll
        for (int j = 0; j < 4; j++) {
            const int c = colBase + tx * 4 + j;
            if (c < N) {
                float v = acc[i][j];
                if (EPI == 1) {
                    v += bias[c];
                    v = (v > 20.f) ? v : log1pf(expf(v));   // softplus
                }
                C[(size_t)r * ldc + c] = v;
            }
        }
    }
}

// ---------------- depthwise causal conv (D_CONV=4) + bias + SiLU ----------------
// input is cols [0, DIN) of g_xr rows (row stride 2*DIN)
__global__ void conv_silu_k(const float* __restrict__ xr,
                            const float* __restrict__ cw,
                            const float* __restrict__ cb,
                            float* __restrict__ xconv)
{
    int idx = blockIdx.x * blockDim.x + threadIdx.x;
    if (idx >= MTOK * DIN) return;
    int c = idx & (DIN - 1);
    int l = (idx >> 11) & (LSEQ - 1);
    int b = idx >> 21;
    float acc = cb[c];
    #pragma unroll
    for (int j = 0; j < 4; j++) {
        int ll = l - 3 + j;
        if (ll >= 0)
            acc = fmaf(xr[((size_t)(b * LSEQ + ll)) * (2 * DIN) + c], cw[j * DIN + c], acc);
    }
    xconv[idx] = acc / (1.f + expf(-acc));   // silu
}

// ---------------- selective scan ----------------
// one thread per (b, d, n): 2*2048*16 = 65536 threads; 16 lanes share a channel.
__global__ __launch_bounds__(256) void scan_k(
    const float* __restrict__ delta, const float* __restrict__ xconv,
    const float* __restrict__ xdbl,  const float* __restrict__ A_log,
    const float* __restrict__ Dv,    float* __restrict__ y)
{
    int t = blockIdx.x * blockDim.x + threadIdx.x;
    int n = t & (DST - 1);
    int d = (t >> 4) & (DIN - 1);
    int b = t >> 15;

    const float A  = -expf(A_log[d * DST + n]);
    const float Dd = Dv[d];

    const float* drow = delta + (size_t)b * LSEQ * DIN + d;
    const float* urow = xconv + (size_t)b * LSEQ * DIN + d;
    const float* brow = xdbl  + (size_t)b * LSEQ * XDBL_W + DTR + n;
    const float* crow = xdbl  + (size_t)b * LSEQ * XDBL_W + DTR + DST + n;
    float*       yrow = y     + (size_t)b * LSEQ * DIN + d;

    float state = 0.f;
    // prefetch l = 0
    float dv = drow[0], uv = urow[0], bv = brow[0], cv = crow[0];

    for (int l = 0; l < LSEQ; l++) {
        float dv_n = 0.f, uv_n = 0.f, bv_n = 0.f, cv_n = 0.f;
        if (l + 1 < LSEQ) {
            dv_n = drow[(size_t)(l + 1) * DIN];
            uv_n = urow[(size_t)(l + 1) * DIN];
            bv_n = brow[(size_t)(l + 1) * XDBL_W];
            cv_n = crow[(size_t)(l + 1) * XDBL_W];
        }
        float dA = expf(dv * A);
        state = fmaf(dA, state, dv * bv * uv);
        float part = state * cv;
        part += __shfl_xor_sync(0xffffffffu, part, 1);
        part += __shfl_xor_sync(0xffffffffu, part, 2);
        part += __shfl_xor_sync(0xffffffffu, part, 4);
        part += __shfl_xor_sync(0xffffffffu, part, 8);
        if (n == 0) yrow[(size_t)l * DIN] = fmaf(uv, Dd, part);
        dv = dv_n; uv = uv_n; bv = bv_n; cv = cv_n;
    }
}

// ---------------- gating: yc = y * silu(res) ----------------
__global__ void gate_k(const float* __restrict__ y, const float* __restrict__ xr,
                       float* __restrict__ yc)
{
    int idx = blockIdx.x * blockDim.x + threadIdx.x;
    if (idx >= MTOK * DIN) return;
    int c = idx & (DIN - 1);
    int row = idx >> 11;
    float res = xr[(size_t)row * (2 * DIN) + DIN + c];
    yc[idx] = y[idx] * res / (1.f + expf(-res));
}

// ---------------- launch ----------------
extern "C" void kernel_launch(void* const* d_in, const int* in_sizes, int n_in,
                              void* d_out, int out_size)
{
    const float* x      = (const float*)d_in[0];
    const float* W_in   = (const float*)d_in[1];
    const float* conv_w = (const float*)d_in[2];
    const float* conv_b = (const float*)d_in[3];
    const float* W_x    = (const float*)d_in[4];
    const float* W_dt   = (const float*)d_in[5];
    const float* b_dt   = (const float*)d_in[6];
    const float* A_log  = (const float*)d_in[7];
    const float* Dvec   = (const float*)d_in[8];
    const float* W_out  = (const float*)d_in[9];
    float* out = (float*)d_out;

    float *xr, *xconv, *xdbl, *delta, *y, *yc;
    cudaGetSymbolAddress((void**)&xr,    g_xr);
    cudaGetSymbolAddress((void**)&xconv, g_xconv);
    cudaGetSymbolAddress((void**)&xdbl,  g_xdbl);
    cudaGetSymbolAddress((void**)&delta, g_delta);
    cudaGetSymbolAddress((void**)&y,     g_y);
    cudaGetSymbolAddress((void**)&yc,    g_yc);

    // 1) x_and_res = x @ W_in      [2048, 4096] = [2048,1024]@[1024,4096]
    sgemm_k<0><<<dim3((2 * DIN) / 64, MTOK / 64), 256>>>(
        x, W_in, nullptr, xr, MTOK, 2 * DIN, DM, DM, 2 * DIN, 2 * DIN);

    // 2) depthwise causal conv + SiLU
    conv_silu_k<<<(MTOK * DIN + 255) / 256, 256>>>(xr, conv_w, conv_b, xconv);

    // 3) x_dbl = x_conv @ W_x      [2048, 96] = [2048,2048]@[2048,96]
    sgemm_k<0><<<dim3((XDBL_W + 63) / 64, MTOK / 64), 256>>>(
        xconv, W_x, nullptr, xdbl, MTOK, XDBL_W, DIN, DIN, XDBL_W, XDBL_W);

    // 4) delta = softplus(x_dbl[:, :64] @ W_dt + b_dt)  [2048, 2048]
    sgemm_k<1><<<dim3(DIN / 64, MTOK / 64), 256>>>(
        xdbl, W_dt, b_dt, delta, MTOK, DIN, DTR, XDBL_W, DIN, DIN);

    // 5) selective scan
    scan_k<<<(BATCH * DIN * DST) / 256, 256>>>(delta, xconv, xdbl, A_log, Dvec, y);

    // 6) gate: yc = y * silu(res)
    gate_k<<<(MTOK * DIN + 255) / 256, 256>>>(y, xr, yc);

    // 7) out = yc @ W_out          [2048, 1024] = [2048,2048]@[2048,1024]
    sgemm_k<0><<<dim3(DM / 64, MTOK / 64), 256>>>(
        yc, W_out, nullptr, out, MTOK, DM, DIN, DIN, DM, DM);
}

// round 3
// speedup vs baseline: 2.6243x; 2.6243x over previous
#include <cuda_runtime.h>
#include <cuda_fp16.h>
#include <math.h>
#include <stdint.h>

#define BATCH 2
#define LSEQ  1024
#define DM    1024
#define DIN   2048
#define DTR   64
#define DST   16
#define XDBL_W 96
#define MTOK  2048

// ======================= PTX helpers =======================
__device__ __forceinline__ uint32_t smem_u32(const void* p){
    uint32_t a;
    asm("{ .reg .u64 t; cvta.to.shared.u64 t, %1; cvt.u32.u64 %0, t; }" : "=r"(a) : "l"(p));
    return a;
}
#define CPA(sa,ga)   asm volatile("cp.async.cg.shared.global [%0], [%1], 16;" :: "r"(sa), "l"(ga) : "memory")
#define CPA_COMMIT() asm volatile("cp.async.commit_group;" ::: "memory")
#define CPA_WAIT(n)  asm volatile("cp.async.wait_group %0;" :: "n"(n) : "memory")

__device__ __forceinline__ void ldsm4(uint32_t* r, uint32_t addr){
    asm volatile("ldmatrix.sync.aligned.m8n8.x4.shared.b16 {%0,%1,%2,%3}, [%4];"
        : "=r"(r[0]), "=r"(r[1]), "=r"(r[2]), "=r"(r[3]) : "r"(addr));
}
__device__ __forceinline__ void mma16816(float* c, const uint32_t* a, const uint32_t* b){
    asm volatile("mma.sync.aligned.m16n8k16.row.col.f32.f16.f16.f32 "
        "{%0,%1,%2,%3}, {%4,%5,%6,%7}, {%8,%9}, {%0,%1,%2,%3};"
        : "+f"(c[0]), "+f"(c[1]), "+f"(c[2]), "+f"(c[3])
        : "r"(a[0]), "r"(a[1]), "r"(a[2]), "r"(a[3]), "r"(b[0]), "r"(b[1]));
}

// ======================= scratch buffers =======================
__device__ __half g_xh  [(size_t)MTOK*DM],   g_xl  [(size_t)MTOK*DM];
__device__ __half g_Winh[(size_t)4096*1024], g_Winl[(size_t)4096*1024];  // [N=4096,K=1024]
__device__ float  g_xr  [(size_t)MTOK*2*DIN];
__device__ float  g_xconv[(size_t)MTOK*DIN];
__device__ __half g_xch [(size_t)MTOK*DIN],  g_xcl [(size_t)MTOK*DIN];
__device__ __half g_Wxh [(size_t)128*DIN],   g_Wxl [(size_t)128*DIN];    // [128pad,K=2048]
__device__ float  g_part[(size_t)8*MTOK*XDBL_W];
__device__ float  g_xdbl[(size_t)MTOK*XDBL_W];
__device__ __half g_dih [(size_t)MTOK*DTR],  g_dil [(size_t)MTOK*DTR];
__device__ __half g_Wdth[(size_t)DIN*DTR],   g_Wdtl[(size_t)DIN*DTR];    // [N=2048,K=64]
__device__ float  g_delta[(size_t)MTOK*DIN];
__device__ float  g_y   [(size_t)MTOK*DIN];
__device__ __half g_ych [(size_t)MTOK*DIN],  g_ycl [(size_t)MTOK*DIN];
__device__ __half g_Woh [(size_t)DM*DIN],    g_Wol [(size_t)DM*DIN];     // [N=1024,K=2048]

// ======================= HMMA GEMM =======================
// C[M,N] = A[M,K] @ Bt[N,K]^T with split-fp16 operands.
// Block 128x128, BK=64, 8 warps (2x4), warp tile 64x32, double-buffered cp.async.
// NTERMS=2: Ah*Bh + Al*Bh ; NTERMS=3: + Ah*Bl.
// EPI=1: softplus(v + bias[col]).
// blockIdx.z = split-K slice; C is offset by z*M*ldc (partial buffers).
#define STAGE 65536
#define GEMM_SMEM (2*STAGE)

template<int NTERMS, int EPI>
__global__ void __launch_bounds__(256,1) gemm_mma(
    const __half* __restrict__ Ah, const __half* __restrict__ Al,
    const __half* __restrict__ Bth, const __half* __restrict__ Btl,
    const float* __restrict__ bias, float* __restrict__ C,
    int M, int N, int Kslice, int lda, int ldb, int ldc)
{
    extern __shared__ __align__(128) char sm[];
    const int tid = threadIdx.x, lane = tid & 31, wid = tid >> 5;
    const int wm = wid & 1, wn = wid >> 1;
    const int rowBase = blockIdx.y * 128, colBase = blockIdx.x * 128;
    const int k0base = blockIdx.z * Kslice;
    C += (size_t)blockIdx.z * M * ldc;
    const int nk = Kslice >> 6;
    const uint32_t sb = smem_u32(sm);

    float acc[4][4][4];
    #pragma unroll
    for (int i=0;i<4;i++)
        #pragma unroll
        for (int j=0;j<4;j++)
            #pragma unroll
            for (int q=0;q<4;q++) acc[i][j][q] = 0.f;

    auto load_chunk = [&](int c, int s){
        const int k0 = k0base + c*64;
        const uint32_t stage = sb + s*STAGE;
        #pragma unroll
        for (int i=0;i<4;i++){
            int idx = i*256 + tid;
            int r = idx >> 3, g = idx & 7;
            uint32_t so = (uint32_t)(r*128 + ((g*16) ^ ((r&7)<<4)));
            CPA(stage + so,         (const void*)(Ah  + (size_t)(rowBase+r)*lda + k0 + g*8));
            CPA(stage + 16384 + so, (const void*)(Al  + (size_t)(rowBase+r)*lda + k0 + g*8));
            CPA(stage + 32768 + so, (const void*)(Bth + (size_t)(colBase+r)*ldb + k0 + g*8));
            if (NTERMS == 3)
                CPA(stage + 49152 + so, (const void*)(Btl + (size_t)(colBase+r)*ldb + k0 + g*8));
        }
        CPA_COMMIT();
    };

    load_chunk(0, 0);

    for (int c=0; c<nk; c++){
        if (c+1 < nk){ load_chunk(c+1, (c+1)&1); CPA_WAIT(1); }
        else         { CPA_WAIT(0); }
        __syncthreads();
        const uint32_t stage = sb + (c&1)*STAGE;

        #pragma unroll
        for (int ks=0; ks<4; ks++){
            uint32_t ahf[4][4], alf[4][4], bhf[2][4], blf[2][4];
            #pragma unroll
            for (int mt=0; mt<4; mt++){
                int row = wm*64 + mt*16 + ((lane>>3)&1)*8 + (lane&7);
                int bc  = ks*32 + (lane>>4)*16;
                uint32_t so = (uint32_t)(row*128 + (bc ^ ((row&7)<<4)));
                ldsm4(ahf[mt], stage + so);
                ldsm4(alf[mt], stage + 16384 + so);
            }
            #pragma unroll
            for (int p=0; p<2; p++){
                int nrow = wn*32 + p*16 + ((lane>>4)&1)*8 + (lane&7);
                int bc   = ks*32 + ((lane>>3)&1)*16;
                uint32_t so = (uint32_t)(nrow*128 + (bc ^ ((nrow&7)<<4)));
                ldsm4(bhf[p], stage + 32768 + so);
                if (NTERMS == 3) ldsm4(blf[p], stage + 49152 + so);
            }
            #pragma unroll
            for (int mt=0; mt<4; mt++)
                #pragma unroll
                for (int nt=0; nt<4; nt++){
                    const uint32_t* b = &bhf[nt>>1][(nt&1)*2];
                    mma16816(acc[mt][nt], ahf[mt], b);
                    mma16816(acc[mt][nt], alf[mt], b);
                    if (NTERMS == 3)
                        mma16816(acc[mt][nt], ahf[mt], &blf[nt>>1][(nt&1)*2]);
                }
        }
        __syncthreads();
    }

    // epilogue
    #pragma unroll
    for (int mt=0; mt<4; mt++){
        int row0 = rowBase + wm*64 + mt*16 + (lane>>2);
        #pragma unroll
        for (int nt=0; nt<4; nt++){
            int col = colBase + wn*32 + nt*8 + (lane&3)*2;
            if (col < N){
                float v0=acc[mt][nt][0], v1=acc[mt][nt][1];
                float v2=acc[mt][nt][2], v3=acc[mt][nt][3];
                if (EPI == 1){
                    float b0 = bias[col], b1 = bias[col+1];
                    v0 += b0; v1 += b1; v2 += b0; v3 += b1;
                    v0 = (v0>20.f)? v0 : log1pf(__expf(v0));
                    v1 = (v1>20.f)? v1 : log1pf(__expf(v1));
                    v2 = (v2>20.f)? v2 : log1pf(__expf(v2));
                    v3 = (v3>20.f)? v3 : log1pf(__expf(v3));
                }
                *(float2*)(C + (size_t)row0*ldc + col)     = make_float2(v0, v1);
                *(float2*)(C + (size_t)(row0+8)*ldc + col) = make_float2(v2, v3);
            }
        }
    }
}

// ======================= elementwise / conversion =======================
__device__ __forceinline__ void split2(float v, __half& h, __half& l){
    h = __float2half_rn(v);
    l = __float2half_rn(v - __half2float(h));
}

__global__ void split_k(const float* __restrict__ src,
                        __half* __restrict__ h, __half* __restrict__ l, int n){
    int i = blockIdx.x*blockDim.x + threadIdx.x;
    if (i >= n) return;
    __half hv, lv; split2(src[i], hv, lv);
    h[i] = hv; l[i] = lv;
}

// transpose + split: W[K,N] fp32 -> Th/Tl[Npad,K] fp16 (rows >= N zero)
__global__ void tconv_k(const float* __restrict__ W,
                        __half* __restrict__ Th, __half* __restrict__ Tl,
                        int K, int N){
    __shared__ float s[32][33];
    int tx = threadIdx.x, ty = threadIdx.y;
    int nb = blockIdx.x*32, kb = blockIdx.y*32;
    #pragma unroll
    for (int r=0;r<4;r++){
        int k = kb + ty + r*8, n = nb + tx;
        s[ty + r*8][tx] = (n < N) ? W[(size_t)k*N + n] : 0.f;
    }
    __syncthreads();
    #pragma unroll
    for (int r=0;r<4;r++){
        int n_out = nb + ty + r*8, kk = kb + tx;
        __half hv, lv; split2(s[tx][ty + r*8], hv, lv);
        Th[(size_t)n_out*K + kk] = hv;
        Tl[(size_t)n_out*K + kk] = lv;
    }
}

// depthwise causal conv + bias + SiLU, fused fp16 split output
__global__ void conv_silu_k(const float* __restrict__ xr,
                            const float* __restrict__ cw, const float* __restrict__ cb,
                            float* __restrict__ xconv,
                            __half* __restrict__ xch, __half* __restrict__ xcl){
    int idx = blockIdx.x*blockDim.x + threadIdx.x;
    if (idx >= MTOK*DIN) return;
    int c = idx & (DIN-1);
    int l = (idx >> 11) & (LSEQ-1);
    int b = idx >> 21;
    float acc = cb[c];
    #pragma unroll
    for (int j=0;j<4;j++){
        int ll = l - 3 + j;
        if (ll >= 0)
            acc = fmaf(xr[((size_t)(b*LSEQ + ll))*(2*DIN) + c], cw[j*DIN + c], acc);
    }
    float sv = acc / (1.f + __expf(-acc));
    xconv[idx] = sv;
    __half hv, lv; split2(sv, hv, lv);
    xch[idx] = hv; xcl[idx] = lv;
}

// reduce split-K partials for xdbl; fused fp16 split of the delta-rank block
__global__ void reduce_xdbl_k(const float* __restrict__ part, float* __restrict__ xdbl,
                              __half* __restrict__ dih, __half* __restrict__ dil){
    int i = blockIdx.x*blockDim.x + threadIdx.x;
    if (i >= MTOK*XDBL_W) return;
    float s = 0.f;
    #pragma unroll
    for (int z=0; z<8; z++) s += part[(size_t)z*MTOK*XDBL_W + i];
    xdbl[i] = s;
    int row = i / 96, col = i - row*96;
    if (col < DTR){
        __half hv, lv; split2(s, hv, lv);
        dih[row*DTR + col] = hv;
        dil[row*DTR + col] = lv;
    }
}

// selective scan: thread per (b,d,n), 16 lanes reduce over n via shuffles
__global__ void __launch_bounds__(256) scan_k(
    const float* __restrict__ delta, const float* __restrict__ xconv,
    const float* __restrict__ xdbl,  const float* __restrict__ A_log,
    const float* __restrict__ Dv,    float* __restrict__ y)
{
    int t = blockIdx.x*blockDim.x + threadIdx.x;
    int n = t & (DST-1);
    int d = (t >> 4) & (DIN-1);
    int b = t >> 15;

    const float A  = -__expf(A_log[d*DST + n]);
    const float Dd = Dv[d];

    const float* drow = delta + (size_t)b*LSEQ*DIN + d;
    const float* urow = xconv + (size_t)b*LSEQ*DIN + d;
    const float* brow = xdbl  + (size_t)b*LSEQ*XDBL_W + DTR + n;
    const float* crow = xdbl  + (size_t)b*LSEQ*XDBL_W + DTR + DST + n;
    float*       yrow = y     + (size_t)b*LSEQ*DIN + d;

    float dv[4], uv[4], bv[4], cv[4];
    float state = 0.f;
    #pragma unroll
    for (int q=0;q<4;q++){
        dv[q] = drow[(size_t)q*DIN];
        uv[q] = urow[(size_t)q*DIN];
        bv[q] = brow[(size_t)q*XDBL_W];
        cv[q] = crow[(size_t)q*XDBL_W];
    }
    for (int l=0; l<LSEQ; l+=4){
        #pragma unroll
        for (int q=0;q<4;q++){
            float d_=dv[q], u_=uv[q], b_=bv[q], c_=cv[q];
            int lp = l + q + 4;
            if (lp < LSEQ){
                dv[q] = drow[(size_t)lp*DIN];
                uv[q] = urow[(size_t)lp*DIN];
                bv[q] = brow[(size_t)lp*XDBL_W];
                cv[q] = crow[(size_t)lp*XDBL_W];
            }
            float dA = __expf(d_*A);
            state = fmaf(dA, state, d_*b_*u_);
            float part = state * c_;
            part += __shfl_xor_sync(0xffffffffu, part, 1);
            part += __shfl_xor_sync(0xffffffffu, part, 2);
            part += __shfl_xor_sync(0xffffffffu, part, 4);
            part += __shfl_xor_sync(0xffffffffu, part, 8);
            if (n==0) yrow[(size_t)(l+q)*DIN] = fmaf(u_, Dd, part);
        }
    }
}

// gate: yc = y * silu(res), fp16 split output
__global__ void gate_k(const float* __restrict__ y, const float* __restrict__ xr,
                       __half* __restrict__ ych, __half* __restrict__ ycl){
    int idx = blockIdx.x*blockDim.x + threadIdx.x;
    if (idx >= MTOK*DIN) return;
    int c = idx & (DIN-1);
    int row = idx >> 11;
    float res = xr[(size_t)row*(2*DIN) + DIN + c];
    float g = y[idx] * res / (1.f + __expf(-res));
    __half hv, lv; split2(g, hv, lv);
    ych[idx] = hv; ycl[idx] = lv;
}

// ======================= launch =======================
extern "C" void kernel_launch(void* const* d_in, const int* in_sizes, int n_in,
                              void* d_out, int out_size)
{
    const float* x      = (const float*)d_in[0];
    const float* W_in   = (const float*)d_in[1];
    const float* conv_w = (const float*)d_in[2];
    const float* conv_b = (const float*)d_in[3];
    const float* W_x    = (const float*)d_in[4];
    const float* W_dt   = (const float*)d_in[5];
    const float* b_dt   = (const float*)d_in[6];
    const float* A_log  = (const float*)d_in[7];
    const float* Dvec   = (const float*)d_in[8];
    const float* W_out  = (const float*)d_in[9];
    float* out = (float*)d_out;

    cudaFuncSetAttribute(gemm_mma<2,0>, cudaFuncAttributeMaxDynamicSharedMemorySize, GEMM_SMEM);
    cudaFuncSetAttribute(gemm_mma<3,0>, cudaFuncAttributeMaxDynamicSharedMemorySize, GEMM_SMEM);
    cudaFuncSetAttribute(gemm_mma<3,1>, cudaFuncAttributeMaxDynamicSharedMemorySize, GEMM_SMEM);

    __half *xh,*xl,*Winh,*Winl,*xch,*xcl,*Wxh,*Wxl,*dih,*dil,*Wdth,*Wdtl,*ych,*ycl,*Woh,*Wol;
    float *xr,*xconv,*part,*xdbl,*delta,*y;
    cudaGetSymbolAddress((void**)&xh, g_xh);       cudaGetSymbolAddress((void**)&xl, g_xl);
    cudaGetSymbolAddress((void**)&Winh, g_Winh);   cudaGetSymbolAddress((void**)&Winl, g_Winl);
    cudaGetSymbolAddress((void**)&xr, g_xr);
    cudaGetSymbolAddress((void**)&xconv, g_xconv);
    cudaGetSymbolAddress((void**)&xch, g_xch);     cudaGetSymbolAddress((void**)&xcl, g_xcl);
    cudaGetSymbolAddress((void**)&Wxh, g_Wxh);     cudaGetSymbolAddress((void**)&Wxl, g_Wxl);
    cudaGetSymbolAddress((void**)&part, g_part);
    cudaGetSymbolAddress((void**)&xdbl, g_xdbl);
    cudaGetSymbolAddress((void**)&dih, g_dih);     cudaGetSymbolAddress((void**)&dil, g_dil);
    cudaGetSymbolAddress((void**)&Wdth, g_Wdth);   cudaGetSymbolAddress((void**)&Wdtl, g_Wdtl);
    cudaGetSymbolAddress((void**)&delta, g_delta);
    cudaGetSymbolAddress((void**)&y, g_y);
    cudaGetSymbolAddress((void**)&ych, g_ych);     cudaGetSymbolAddress((void**)&ycl, g_ycl);
    cudaGetSymbolAddress((void**)&Woh, g_Woh);     cudaGetSymbolAddress((void**)&Wol, g_Wol);

    dim3 tb(32,8);

    // weight conversions (transpose + fp16 split)
    tconv_k<<<dim3(128, 32), tb>>>(W_in,  Winh, Winl, 1024, 4096);
    tconv_k<<<dim3(4,   64), tb>>>(W_x,   Wxh,  Wxl,  2048, 96);
    tconv_k<<<dim3(64,  2),  tb>>>(W_dt,  Wdth, Wdtl, 64,   2048);
    tconv_k<<<dim3(32,  64), tb>>>(W_out, Woh,  Wol,  2048, 1024);

    // x -> fp16 split
    split_k<<<(MTOK*DM + 255)/256, 256>>>(x, xh, xl, MTOK*DM);

    // G1: xr = x @ W_in   [2048,4096], K=1024, 2-term
    gemm_mma<2,0><<<dim3(32, 16, 1), 256, GEMM_SMEM>>>(
        xh, xl, Winh, Winl, nullptr, xr, MTOK, 4096, 1024, 1024, 1024, 4096);

    // conv + silu (+ split)
    conv_silu_k<<<(MTOK*DIN + 255)/256, 256>>>(xr, conv_w, conv_b, xconv, xch, xcl);

    // G3: xdbl = xconv @ W_x  [2048,96], K=2048, 3-term, split-K=8 -> partials
    gemm_mma<3,0><<<dim3(1, 16, 8), 256, GEMM_SMEM>>>(
        xch, xcl, Wxh, Wxl, nullptr, part, MTOK, 96, 256, 2048, 2048, 96);
    reduce_xdbl_k<<<(MTOK*XDBL_W + 255)/256, 256>>>(part, xdbl, dih, dil);

    // G4: delta = softplus(xdbl[:,:64] @ W_dt + b_dt)  [2048,2048], K=64, 3-term
    gemm_mma<3,1><<<dim3(16, 16, 1), 256, GEMM_SMEM>>>(
        dih, dil, Wdth, Wdtl, b_dt, delta, MTOK, 2048, 64, 64, 64, 2048);

    // selective scan
    scan_k<<<(BATCH*DIN*DST)/256, 256>>>(delta, xconv, xdbl, A_log, Dvec, y);

    // gate (+ split)
    gate_k<<<(MTOK*DIN + 255)/256, 256>>>(y, xr, ych, ycl);

    // G7: out = yc @ W_out  [2048,1024], K=2048, 2-term
    gemm_mma<2,0><<<dim3(8, 16, 1), 256, GEMM_SMEM>>>(
        ych, ycl, Woh, Wol, nullptr, out, MTOK, 1024, 2048, 2048, 2048, 1024);
}